// round 2
// baseline (speedup 1.0000x reference)
#include <cuda_runtime.h>

// Controlled 2-qubit gate on a 2^26 fp32 statevector.
// Targets: qubits 0,1 -> bits 25,24 of flat index. Control: qubit 2 -> bit 23.
// float4-granule stream: i in [0, 2^22) per t-stream; element base = 4*i,
// control bit = bit 21 of i. Threads handle one copy group (bit21=0) and one
// gate group (bit21=1) each -> zero branching, MLP=8 front-batched loads.

#define QGRP (1 << 22)   // float4 granules per t-stream (2^24 floats / 4)
#define HALF (1 << 21)   // granules with control bit clear

__global__ void __launch_bounds__(256) gate_kernel(
    const float4* __restrict__ in4,
    const float*  __restrict__ m,
    float4*       __restrict__ out4)
{
    const int tid = blockIdx.x * blockDim.x + threadIdx.x;  // 0 .. 2^21-1
    const int gc = tid;          // copy group  (bit 21 == 0 -> control off)
    const int gg = tid + HALF;   // gate group  (bit 21 == 1 -> control on)

    // Front-batch all 8 independent loads (evict-streaming).
    float4 c0 = __ldcs(in4 + gc);
    float4 c1 = __ldcs(in4 + gc + QGRP);
    float4 c2 = __ldcs(in4 + gc + 2 * QGRP);
    float4 c3 = __ldcs(in4 + gc + 3 * QGRP);
    float4 a0 = __ldcs(in4 + gg);
    float4 a1 = __ldcs(in4 + gg + QGRP);
    float4 a2 = __ldcs(in4 + gg + 2 * QGRP);
    float4 a3 = __ldcs(in4 + gg + 3 * QGRP);

    // Copy path stores can retire as soon as their loads land.
    __stcs(out4 + gc,            c0);
    __stcs(out4 + gc + QGRP,     c1);
    __stcs(out4 + gc + 2 * QGRP, c2);
    __stcs(out4 + gc + 3 * QGRP, c3);

    const float m00 = __ldg(m + 0),  m01 = __ldg(m + 1),  m02 = __ldg(m + 2),  m03 = __ldg(m + 3);
    const float m10 = __ldg(m + 4),  m11 = __ldg(m + 5),  m12 = __ldg(m + 6),  m13 = __ldg(m + 7);
    const float m20 = __ldg(m + 8),  m21 = __ldg(m + 9),  m22 = __ldg(m + 10), m23 = __ldg(m + 11);
    const float m30 = __ldg(m + 12), m31 = __ldg(m + 13), m32 = __ldg(m + 14), m33 = __ldg(m + 15);

    float4 y0, y1, y2, y3;
    #define APPLY(c) \
        y0.c = m00 * a0.c + m01 * a1.c + m02 * a2.c + m03 * a3.c; \
        y1.c = m10 * a0.c + m11 * a1.c + m12 * a2.c + m13 * a3.c; \
        y2.c = m20 * a0.c + m21 * a1.c + m22 * a2.c + m23 * a3.c; \
        y3.c = m30 * a0.c + m31 * a1.c + m32 * a2.c + m33 * a3.c;
    APPLY(x); APPLY(y); APPLY(z); APPLY(w);
    #undef APPLY

    __stcs(out4 + gg,            y0);
    __stcs(out4 + gg + QGRP,     y1);
    __stcs(out4 + gg + 2 * QGRP, y2);
    __stcs(out4 + gg + 3 * QGRP, y3);
}

extern "C" void kernel_launch(void* const* d_in, const int* in_sizes, int n_in,
                              void* d_out, int out_size)
{
    const float* x = (const float*)d_in[0];   // 2^26 floats
    const float* m = (const float*)d_in[1];   // 16 floats (4x4 row-major)
    float* out = (float*)d_out;               // 2^26 floats

    const int n_threads = HALF;               // 2^21 threads
    const int block = 256;
    const int grid = n_threads / block;       // 8192
    gate_kernel<<<grid, block>>>((const float4*)x, m, (float4*)out);
}